// round 17
// baseline (speedup 1.0000x reference)
#include <cuda_runtime.h>
#include <cuda_bf16.h>

// Contamination: out = 0.8*x + 0.2 * avg(valid neighbors at {-8,0,8}^2 \ {0,0})
// x: [B=8, C=32, H=512, W=512] fp32, k=8.
//
// R17 = R16 (95.2us; 64-row column march, depth-2 center prefetch, 32 regs,
// 8192 CTAs = 6.92 waves) with the loop body SPECIALIZED for interior
// y-groups (blockIdx.y = 1..6, 75% of CTAs): there nr==3 and all rows valid,
// so the scale constant is hoisted out of the loop and all loads/stores use
// constant immediate offsets off one rolling pointer (p += K*W4). Cuts the
// per-iteration ALU/issue overhead (alu was 38.6%, issue 54.9%) that was
// stealing issue slots from the batched load stream. Boundary groups
// (y=0, y=7) keep the generic validated R16 loop.

namespace {

constexpr int H  = 512;
constexpr int W  = 512;
constexpr int K  = 8;
constexpr int W4 = W / 4;        // 128 float4 per row
constexpr int GROUP_ROWS = 64;   // rows per CTA
constexpr int ITERS = GROUP_ROWS / 8;  // 8 iterations per thread
constexpr int RSTRIDE = K * W4;  // float4 stride between K-adjacent rows

__device__ __forceinline__ float4 f4zero() { return make_float4(0.f, 0.f, 0.f, 0.f); }

__device__ __forceinline__ float4 f4add(float4 a, float4 b) {
    return make_float4(a.x + b.x, a.y + b.y, a.z + b.z, a.w + b.w);
}

__global__ __launch_bounds__(256, 8)
void contam_kernel(const float4* __restrict__ in, float4* __restrict__ out) {
    const int c4   = blockIdx.x * 32 + threadIdx.x;          // float4 column, 0..127
    const int row0 = blockIdx.y * GROUP_ROWS + threadIdx.y;  // first output row
    const int plane = blockIdx.z;

    const float4* __restrict__ pin  = in  + (size_t)plane * (H * W4);
    float4* __restrict__       pout = out + (size_t)plane * (H * W4);

    const bool hasL = (c4 >= 2);
    const bool hasR = (c4 <= W4 - 3);
    const int  nc   = 1 + (int)hasL + (int)hasR;

    // ---- prologue: Sprev (row0-K sum), Scur (row0 sum), cN = center(row0+K) ----
    float4 Sprev = f4zero();
    if (row0 >= K) {
        const float4* __restrict__ r = pin + (row0 - K) * W4;
        Sprev = r[c4];
        if (hasL) Sprev = f4add(Sprev, r[c4 - 2]);
        if (hasR) Sprev = f4add(Sprev, r[c4 + 2]);
    }
    float4 Scur;
    {
        const float4* __restrict__ r = pin + row0 * W4;
        Scur = r[c4];
        if (hasL) Scur = f4add(Scur, r[c4 - 2]);
        if (hasR) Scur = f4add(Scur, r[c4 + 2]);
    }
    float4 cN = pin[(row0 + K) * W4 + c4];   // row0+K <= 503: always valid

    if (blockIdx.y != 0 && blockIdx.y != gridDim.y - 1) {
        // ================= interior path (y = 1..6): nr==3, all rows valid,
        // no clamps; scale hoisted; constant-offset loads off rolling pointer.
        const float scale = (nc == 3) ? 0.025f : 0.04f;   // 0.2/8 : 0.2/5

        const float4* __restrict__ p = pin + row0 * W4 + c4;   // &row[h][c4]
        float4* __restrict__       q = pout + row0 * W4 + c4;

        #pragma unroll
        for (int ry = 0; ry < ITERS; ry++) {
            // batched: ctr (L1 hit), sides of row h+K (mostly L1 hits),
            // prefetch center of h+2K (the one DRAM miss)
            float4 ctr = p[0];
            float4 s0  = hasL ? p[RSTRIDE - 2] : f4zero();
            float4 s2  = hasR ? p[RSTRIDE + 2] : f4zero();
            float4 cN2 = p[2 * RSTRIDE];

            float4 Snext = f4add(f4add(cN, s0), s2);
            float4 acc   = f4add(f4add(Sprev, Scur), Snext);

            float4 o;
            o.x = 0.8f * ctr.x + scale * (acc.x - ctr.x);
            o.y = 0.8f * ctr.y + scale * (acc.y - ctr.y);
            o.z = 0.8f * ctr.z + scale * (acc.z - ctr.z);
            o.w = 0.8f * ctr.w + scale * (acc.w - ctr.w);

            __stcs(q, o);

            Sprev = Scur;
            Scur  = Snext;
            cN    = cN2;
            p += RSTRIDE;
            q += RSTRIDE;
        }
    } else {
        // ================= boundary path (y = 0 or last): generic R16 loop.
        #pragma unroll 4
        for (int ry = 0; ry < ITERS; ry++) {
            const int h   = row0 + ry * K;
            const int rn  = h + K;
            const bool vn = (rn < H);
            const int rn2 = h + 2 * K;
            const int rn2c = (rn2 < H) ? rn2 : h;   // clamped legal address

            const float4* __restrict__ rowC = pin + h * W4;
            const float4* __restrict__ rowN = pin + (vn ? rn : h) * W4;
            float4 ctr = rowC[c4];
            float4 s0  = hasL ? rowN[c4 - 2] : f4zero();
            float4 s2  = hasR ? rowN[c4 + 2] : f4zero();
            float4 cN2 = pin[rn2c * W4 + c4];

            float4 Snext = vn ? f4add(f4add(cN, s0), s2) : f4zero();

            const int nr = 1 + (int)(h >= K) + (int)vn;
            // count = nr*nc - 1 in {3,5,8}  <=>  nr+nc in {4,5,6}
            const int s  = nr + nc;
            const float scale = (s == 6) ? 0.025f
                              : (s == 5) ? 0.04f
                                         : 0.066666667f;

            float4 acc = f4add(f4add(Sprev, Scur), Snext);

            float4 o;
            o.x = 0.8f * ctr.x + scale * (acc.x - ctr.x);
            o.y = 0.8f * ctr.y + scale * (acc.y - ctr.y);
            o.z = 0.8f * ctr.z + scale * (acc.z - ctr.z);
            o.w = 0.8f * ctr.w + scale * (acc.w - ctr.w);

            __stcs(&pout[h * W4 + c4], o);

            Sprev = Scur;
            Scur  = Snext;
            cN    = cN2;
        }
    }
}

} // namespace

extern "C" void kernel_launch(void* const* d_in, const int* in_sizes, int n_in,
                              void* d_out, int out_size) {
    const float4* x = (const float4*)d_in[0];
    float4* out = (float4*)d_out;

    const int planes = in_sizes[0] / (H * W);   // 256

    dim3 block(32, 8, 1);
    dim3 grid(W4 / 32, H / GROUP_ROWS, planes); // (4, 8, 256) = 8192 CTAs
    contam_kernel<<<grid, block>>>(x, out);
}